// round 2
// baseline (speedup 1.0000x reference)
#include <cuda_runtime.h>

#define E 8
#define DDIM 1024
#define TILE_T 256
#define NTHREADS 256
#define CHUNK 32
#define NCHUNK (DDIM / CHUNK)
#define STAGES 4
#define SMEM_BYTES ((E * DDIM + STAGES * TILE_T * CHUNK) * 4)

// Global accumulators (scratch; no allocations allowed)
__device__ float g_prob_sum[E];
__device__ float g_ent_sum;
__device__ unsigned g_cnt[E];

__global__ void zero_accum() {
    int i = threadIdx.x;
    if (i < E) { g_prob_sum[i] = 0.f; g_cnt[i] = 0u; }
    if (i == 0) g_ent_sum = 0.f;
}

__device__ __forceinline__ void issue_chunk(const float* __restrict__ x, float4* sx4,
                                            int tok_base, int c, int tid, int N) {
    int buf = c & (STAGES - 1);
#pragma unroll
    for (int r = 0; r < (TILE_T * CHUNK / 4) / NTHREADS; ++r) {
        int idx = tid + r * NTHREADS;
        int tl = idx >> 3;      // local token
        int j  = idx & 7;       // float4 index within chunk
        int tok = tok_base + tl;
        if (tok >= N) tok = N - 1;
        const float* src = x + (size_t)tok * DDIM + c * CHUNK + j * 4;
        float4* dptr = &sx4[((buf * TILE_T + tl) << 3) + (j ^ (tl & 7))];
        unsigned dst = (unsigned)__cvta_generic_to_shared(dptr);
        asm volatile("cp.async.cg.shared.global [%0], [%1], 16;\n" :: "r"(dst), "l"(src));
    }
    asm volatile("cp.async.commit_group;\n");
}

__global__ __launch_bounds__(NTHREADS, 1)
void router_main(const float* __restrict__ x, const float* __restrict__ Wg,
                 const int* __restrict__ pk, float* __restrict__ out, int N) {
    extern __shared__ float smem[];
    float* sW = smem;                              // [E * DDIM]
    float4* sx4 = (float4*)(smem + E * DDIM);      // [STAGES][TILE_T][8] swizzled

    int tid = threadIdx.x;
    int tok_base = blockIdx.x * TILE_T;
    int token = tok_base + tid;
    bool valid = token < N;

    // Prologue: get HBM moving before anything else
    for (int c = 0; c < STAGES - 1; ++c) issue_chunk(x, sx4, tok_base, c, tid, N);

    // Stage W (32KB) into shared
    for (int i = tid; i < E * DDIM; i += NTHREADS) sW[i] = Wg[i];

    float acc[E];
#pragma unroll
    for (int e = 0; e < E; ++e) acc[e] = 0.f;

    int sw = tid & 7;
    for (int c = 0; c < NCHUNK; ++c) {
        if (c >= NCHUNK - 2) asm volatile("cp.async.wait_group 0;\n" ::: "memory");
        else                 asm volatile("cp.async.wait_group %0;\n" :: "n"(STAGES - 2) : "memory");
        __syncthreads();
        const float4* xs = &sx4[((c & (STAGES - 1)) * TILE_T + tid) << 3];
#pragma unroll
        for (int j = 0; j < CHUNK / 4; ++j) {
            float4 xv = xs[j ^ sw];
            int d = c * CHUNK + j * 4;
#pragma unroll
            for (int e = 0; e < E; ++e) {
                const float4 wv = *(const float4*)(sW + e * DDIM + d); // warp-uniform broadcast
                acc[e] = fmaf(xv.x, wv.x, acc[e]);
                acc[e] = fmaf(xv.y, wv.y, acc[e]);
                acc[e] = fmaf(xv.z, wv.z, acc[e]);
                acc[e] = fmaf(xv.w, wv.w, acc[e]);
            }
        }
        if (c + STAGES - 1 < NCHUNK)
            issue_chunk(x, sx4, tok_base, c + STAGES - 1, tid, N);
    }

    // ---- epilogue: softmax / top-k / stats, all in registers ----
    int kk = *pk; kk = kk < 1 ? 1 : (kk > E ? E : kk);
    float* out_dw  = out;
    float* out_idx = out + (size_t)N * kk;
    float* out_lg  = out + (size_t)2 * N * kk;

    if (valid) {
        float4* lp = (float4*)(out_lg + (size_t)token * E);
        lp[0] = make_float4(acc[0], acc[1], acc[2], acc[3]);
        lp[1] = make_float4(acc[4], acc[5], acc[6], acc[7]);
    }

    float m = acc[0];
#pragma unroll
    for (int e = 1; e < E; ++e) m = fmaxf(m, acc[e]);
    float p[E], s = 0.f;
#pragma unroll
    for (int e = 0; e < E; ++e) { p[e] = __expf(acc[e] - m); s += p[e]; }
    float inv = 1.f / s;
    float logs = __logf(s);
    float ent = 0.f;
#pragma unroll
    for (int e = 0; e < E; ++e) ent -= (p[e] * inv) * (acc[e] - m - logs);

    // top-k (values descending, ties -> lower index, matching lax.top_k)
    unsigned selmask = 0;
    float tmp[E];
#pragma unroll
    for (int e = 0; e < E; ++e) tmp[e] = p[e];
#pragma unroll
    for (int r = 0; r < E; ++r) {
        if (r < kk) {
            int bi = 0; float bv = tmp[0];
#pragma unroll
            for (int e = 1; e < E; ++e) { if (tmp[e] > bv) { bv = tmp[e]; bi = e; } }
            if (valid) {
                out_dw [(size_t)token * kk + r] = bv * inv;
                out_idx[(size_t)token * kk + r] = (float)bi;
            }
            selmask |= (1u << bi);
#pragma unroll
            for (int e = 0; e < E; ++e) if (e == bi) tmp[e] = -1.f;
        }
    }

    if (!valid) { ent = 0.f; selmask = 0u; inv = 0.f; }

    // warp-level reductions, then one set of global atomics per warp
    float entw = ent;
#pragma unroll
    for (int o = 16; o > 0; o >>= 1) entw += __shfl_xor_sync(0xffffffffu, entw, o);
    float psum[E];
#pragma unroll
    for (int e = 0; e < E; ++e) {
        float v = p[e] * inv;
#pragma unroll
        for (int o = 16; o > 0; o >>= 1) v += __shfl_xor_sync(0xffffffffu, v, o);
        psum[e] = v;
    }
    bool lane0 = (tid & 31) == 0;
    if (lane0) atomicAdd(&g_ent_sum, entw);
#pragma unroll
    for (int e = 0; e < E; ++e) {
        unsigned b = __ballot_sync(0xffffffffu, (selmask >> e) & 1u);
        if (lane0) {
            atomicAdd(&g_cnt[e], (unsigned)__popc(b));
            atomicAdd(&g_prob_sum[e], psum[e]);
        }
    }
}

__global__ void finalize_kernel(const int* __restrict__ pk, float* __restrict__ out, int N) {
    if (threadIdx.x != 0 || blockIdx.x != 0) return;
    int kk = *pk; kk = kk < 1 ? 1 : (kk > E ? E : kk);
    float* base = out + (size_t)2 * N * kk + (size_t)N * E;
    long long total_cap = (long long)((double)N * (double)kk * 1.25);
    long long per_cap = total_cap / E; if (per_cap < 1) per_cap = 1;
    float invN = 1.f / (float)N;
    float lb = 0.f; int nd = 0;
    for (int e = 0; e < E; ++e) {
        float cnt = (float)g_cnt[e];
        float usage = cnt * invN;
        float avg = g_prob_sum[e] * invN;
        lb += usage * avg;
        if ((long long)g_cnt[e] > per_cap) nd++;
        base[3 + e] = usage;
    }
    base[0] = lb * (float)E;
    float entm = g_ent_sum * invN;
    float rel = logf((float)E) - entm;
    base[1] = rel > 0.f ? rel : 0.f;
    base[2] = (float)nd;
}

extern "C" void kernel_launch(void* const* d_in, const int* in_sizes, int n_in,
                              void* d_out, int out_size) {
    const float* x = (const float*)d_in[0];
    const float* W = (const float*)d_in[1];
    const int*  pk = (const int*)d_in[2];
    int N = in_sizes[0] / DDIM;
    float* out = (float*)d_out;

    cudaFuncSetAttribute(router_main, cudaFuncAttributeMaxDynamicSharedMemorySize, SMEM_BYTES);

    zero_accum<<<1, 32>>>();
    int grid = (N + TILE_T - 1) / TILE_T;
    router_main<<<grid, NTHREADS, SMEM_BYTES>>>(x, W, pk, out, N);
    finalize_kernel<<<1, 32>>>(pk, out, N);
}